// round 13
// baseline (speedup 1.0000x reference)
#include <cuda_runtime.h>

// ---------------------------------------------------------------------------
// FrequencyAwareEmbedding, round 13.  ONE fused kernel.
//   blocks [0, NBUILD)          : project bucket-3/4 rows into g_proj
//                                 (smem compaction + LDS.128 broadcast),
//                                 then atomicAdd(g_done).
//   blocks [NBUILD, NBUILD+NG)  : gather, 4 tokens per 8-thread group:
//                                 probe buckets, store bucket-0..2 rows
//                                 immediately (overlaps projection), spin on
//                                 g_done, then store bucket-3/4 rows.
//   Replay-safe flag reset: last gather block past the spin zeroes g_done
//   and g_passed (all blocks sync before counting, so no lost wakeups).
//   Producers own the lowest block ids -> resident in wave 1 -> no deadlock.
// ---------------------------------------------------------------------------

#define NROWS   100000
#define ODIM    32
#define PADK51  52
#define PADK102 104
#define NBUILD  391          // ceil(100000/256)

__device__ __align__(256) float g_proj[NROWS * ODIM];
__device__ int g_done;       // stage blocks completed (0 at every replay start)
__device__ int g_passed;     // gather blocks past the spin (idem)

// --- project one dense group of <=8 rows (row ids in smem list) ---
template <int K, int PADK>
__device__ __forceinline__ void proj_group(const int* __restrict__ slist,
                                           int gbase, int cnt,
                                           const float* __restrict__ emb,
                                           const float* __restrict__ W,
                                           const float* __restrict__ b,
                                           float* __restrict__ out,
                                           float* __restrict__ es,  // 8*PADK
                                           int lane)
{
    constexpr int CH = (PADK + 31) / 32;
    constexpr int Q  = (K + 3) / 4;

    int nv = cnt - gbase;
    if (nv > 8) nv = 8;

    int rws[8];
    #pragma unroll
    for (int g = 0; g < 8; ++g)
        rws[g] = slist[gbase + (g < nv ? g : 0)];

    #pragma unroll
    for (int g = 0; g < 8; ++g) {
        #pragma unroll
        for (int ch = 0; ch < CH; ++ch) {
            int k = ch * 32 + lane;
            if (k < PADK)
                es[g * PADK + k] =
                    (k < K) ? __ldg(&emb[(size_t)rws[g] * K + k]) : 0.0f;
        }
    }
    __syncwarp();

    float bias = __ldg(&b[lane]);
    float acc[8];
    #pragma unroll
    for (int g = 0; g < 8; ++g) acc[g] = bias;

    #pragma unroll
    for (int q = 0; q < Q; ++q) {
        int k0 = q * 4;
        float w0 = __ldg(&W[(k0 + 0) * 32 + lane]);
        float w1 = (k0 + 1 < K) ? __ldg(&W[(k0 + 1) * 32 + lane]) : 0.0f;
        float w2 = (k0 + 2 < K) ? __ldg(&W[(k0 + 2) * 32 + lane]) : 0.0f;
        float w3 = (k0 + 3 < K) ? __ldg(&W[(k0 + 3) * 32 + lane]) : 0.0f;

        #pragma unroll
        for (int g = 0; g < 8; ++g) {
            float4 e4 = *reinterpret_cast<const float4*>(&es[g * PADK + k0]);
            acc[g] = fmaf(e4.x, w0, acc[g]);
            acc[g] = fmaf(e4.y, w1, acc[g]);
            acc[g] = fmaf(e4.z, w2, acc[g]);
            acc[g] = fmaf(e4.w, w3, acc[g]);
        }
    }
    __syncwarp();

    #pragma unroll
    for (int g = 0; g < 8; ++g)
        if (g < nv)
            out[(size_t)rws[g] * ODIM + lane] = acc[g];
}

__global__ void __launch_bounds__(256)
fused(const int4*   __restrict__ x4,
      const int*    __restrict__ bucket,
      const float4* __restrict__ e0,
      const float4* __restrict__ e1,
      const float4* __restrict__ e2,
      const float*  __restrict__ emb3,
      const float*  __restrict__ W3,
      const float*  __restrict__ b3,
      const float*  __restrict__ emb4,
      const float*  __restrict__ W4,
      const float*  __restrict__ b4,
      float4*       __restrict__ out,
      int rows, int Tg4, int ngather)
{
    __shared__ __align__(16) float es[8][8 * PADK102];   // 26.6 KB
    __shared__ int sl3[256], sl4[256];
    __shared__ int sc3, sc4;

    int tid  = threadIdx.x;
    int warp = tid >> 5;
    int lane = tid & 31;

    if (blockIdx.x < NBUILD) {
        // ================= stage: project bucket-3/4 rows =================
        if (tid == 0) { sc3 = 0; sc4 = 0; }
        __syncthreads();

        int r  = blockIdx.x * 256 + tid;
        int bk = (r < rows) ? __ldg(&bucket[r]) : -1;

        unsigned m3 = __ballot_sync(0xffffffffu, bk == 3);
        unsigned m4 = __ballot_sync(0xffffffffu, bk == 4);
        unsigned lt = (1u << lane) - 1u;

        if (bk == 3) {
            int base = 0;
            int ldr = __ffs(m3) - 1;
            if (lane == ldr) base = atomicAdd(&sc3, __popc(m3));
            base = __shfl_sync(m3, base, ldr);
            sl3[base + __popc(m3 & lt)] = r;
        }
        if (bk == 4) {
            int base = 0;
            int ldr = __ffs(m4) - 1;
            if (lane == ldr) base = atomicAdd(&sc4, __popc(m4));
            base = __shfl_sync(m4, base, ldr);
            sl4[base + __popc(m4 & lt)] = r;
        }
        __syncthreads();

        int n3 = sc3, n4 = sc4;
        int n3g = (n3 + 7) >> 3;
        int n4g = (n4 + 7) >> 3;
        int ng  = n3g + n4g;

        float* proj = &g_proj[0];
        for (int g = warp; g < ng; g += 8) {
            if (g < n3g)
                proj_group<51,  PADK51 >(sl3, g * 8, n3, emb3, W3, b3,
                                         proj, es[warp], lane);
            else
                proj_group<102, PADK102>(sl4, (g - n3g) * 8, n4, emb4, W4, b4,
                                         proj, es[warp], lane);
        }

        __syncthreads();
        if (tid == 0) {
            __threadfence();
            atomicAdd(&g_done, 1);
        }
        return;
    }

    // ================= gather: 4 tokens per 8-thread group =================
    int gid = (blockIdx.x - NBUILD) * 256 + tid;
    int grp = gid >> 3;
    int c   = gid & 7;
    bool active = grp < Tg4;

    int idx[4], bk[4];
    if (active) {
        int4 ia = __ldg(&x4[grp]);
        idx[0] = ia.x; idx[1] = ia.y; idx[2] = ia.z; idx[3] = ia.w;

        #pragma unroll
        for (int j = 0; j < 4; ++j)
            bk[j] = __ldg(&bucket[idx[j]]);

        // bucket 0..2 rows: no dependency on projection — do them NOW.
        float4 v[4];
        bool   st[4];
        #pragma unroll
        for (int j = 0; j < 4; ++j) {
            st[j] = (bk[j] <= 2);
            const float4* t = (bk[j] == 0) ? e0 : (bk[j] == 1) ? e1 : e2;
            if (st[j]) v[j] = __ldg(&t[(size_t)idx[j] * 8 + c]);
        }
        #pragma unroll
        for (int j = 0; j < 4; ++j)
            if (st[j])
                __stcs(&out[(size_t)(grp * 4 + j) * 8 + c], v[j]);
    }

    // wait for projection producers
    if (*(volatile int*)&g_done < NBUILD) {
        while (*(volatile int*)&g_done < NBUILD)
            __nanosleep(128);
    }
    __threadfence();

    if (active) {
        const float4* pj = reinterpret_cast<const float4*>(&g_proj[0]);
        float4 v[4];
        bool   st[4];
        #pragma unroll
        for (int j = 0; j < 4; ++j) {
            st[j] = (bk[j] >= 3);
            if (st[j]) v[j] = __ldg(&pj[(size_t)idx[j] * 8 + c]);
        }
        #pragma unroll
        for (int j = 0; j < 4; ++j)
            if (st[j])
                __stcs(&out[(size_t)(grp * 4 + j) * 8 + c], v[j]);
    }

    // replay-safe reset: all threads of the block are past the spin here.
    __syncthreads();
    if (tid == 0) {
        int old = atomicAdd(&g_passed, 1);
        if (old == ngather - 1) {
            g_done = 0;
            __threadfence();
            g_passed = 0;
            __threadfence();
        }
    }
}

extern "C" void kernel_launch(void* const* d_in, const int* in_sizes, int n_in,
                              void* d_out, int out_size)
{
    const int*   x      = (const int*)  d_in[0];
    const int*   bucket = (const int*)  d_in[1];
    const float* emb0   = (const float*)d_in[2];
    const float* emb1   = (const float*)d_in[3];
    const float* emb2   = (const float*)d_in[4];
    const float* emb3   = (const float*)d_in[5];
    const float* emb4   = (const float*)d_in[6];
    const float* W3     = (const float*)d_in[7];
    const float* b3     = (const float*)d_in[8];
    const float* W4     = (const float*)d_in[9];
    const float* b4     = (const float*)d_in[10];

    const int T    = in_sizes[0];          // 1,048,576 tokens (multiple of 4)
    const int rows = in_sizes[1];          // 100,000

    const int Tg4     = T / 4;                       // 262,144 groups
    const int ngather = (Tg4 * 8 + 255) / 256;       // 8192 gather blocks

    fused<<<NBUILD + ngather, 256>>>(
        (const int4*)x, bucket,
        (const float4*)emb0, (const float4*)emb1, (const float4*)emb2,
        emb3, W3, b3, emb4, W4, b4,
        (float4*)d_out, rows, Tg4, ngather);
}

// round 14
// speedup vs baseline: 1.3159x; 1.3159x over previous
#include <cuda_runtime.h>

// ---------------------------------------------------------------------------
// FrequencyAwareEmbedding, round 14.  ONE fused kernel (round-13 structure,
// occupancy fixed via __launch_bounds__(256, 6) -> <=42 regs; the proj path
// spills a little to local, the gather path (dominant) runs at 75% occ).
//
//   blocks [0, NBUILD)          : project bucket-3/4 rows into g_proj,
//                                 then atomicAdd(g_done).
//   blocks [NBUILD, NBUILD+NG)  : gather, 4 tokens per 8-thread group:
//                                 probe buckets, store bucket-0..2 rows
//                                 immediately (overlaps projection), spin on
//                                 g_done (nanosleep), then bucket-3/4 rows.
//   Replay-safe reset: last gather block past the spin zeroes the flags.
//   Producers own the lowest block ids -> resident in wave 1 -> no deadlock.
// ---------------------------------------------------------------------------

#define NROWS   100000
#define ODIM    32
#define PADK51  52
#define PADK102 104
#define NBUILD  391          // ceil(100000/256)

__device__ __align__(256) float g_proj[NROWS * ODIM];
__device__ int g_done;       // producers completed (0 at every replay start)
__device__ int g_passed;     // gather blocks past the spin (idem)

// --- project one dense group of <=8 rows (row ids in smem list) ---
template <int K, int PADK>
__device__ __forceinline__ void proj_group(const int* __restrict__ slist,
                                           int gbase, int cnt,
                                           const float* __restrict__ emb,
                                           const float* __restrict__ W,
                                           const float* __restrict__ b,
                                           float* __restrict__ out,
                                           float* __restrict__ es,  // 8*PADK
                                           int lane)
{
    constexpr int CH = (PADK + 31) / 32;
    constexpr int Q  = (K + 3) / 4;

    int nv = cnt - gbase;
    if (nv > 8) nv = 8;

    int rws[8];
    #pragma unroll
    for (int g = 0; g < 8; ++g)
        rws[g] = slist[gbase + (g < nv ? g : 0)];

    #pragma unroll
    for (int g = 0; g < 8; ++g) {
        #pragma unroll
        for (int ch = 0; ch < CH; ++ch) {
            int k = ch * 32 + lane;
            if (k < PADK)
                es[g * PADK + k] =
                    (k < K) ? __ldg(&emb[(size_t)rws[g] * K + k]) : 0.0f;
        }
    }
    __syncwarp();

    float bias = __ldg(&b[lane]);
    float acc[8];
    #pragma unroll
    for (int g = 0; g < 8; ++g) acc[g] = bias;

    #pragma unroll
    for (int q = 0; q < Q; ++q) {
        int k0 = q * 4;
        float w0 = __ldg(&W[(k0 + 0) * 32 + lane]);
        float w1 = (k0 + 1 < K) ? __ldg(&W[(k0 + 1) * 32 + lane]) : 0.0f;
        float w2 = (k0 + 2 < K) ? __ldg(&W[(k0 + 2) * 32 + lane]) : 0.0f;
        float w3 = (k0 + 3 < K) ? __ldg(&W[(k0 + 3) * 32 + lane]) : 0.0f;

        #pragma unroll
        for (int g = 0; g < 8; ++g) {
            float4 e4 = *reinterpret_cast<const float4*>(&es[g * PADK + k0]);
            acc[g] = fmaf(e4.x, w0, acc[g]);
            acc[g] = fmaf(e4.y, w1, acc[g]);
            acc[g] = fmaf(e4.z, w2, acc[g]);
            acc[g] = fmaf(e4.w, w3, acc[g]);
        }
    }
    __syncwarp();

    #pragma unroll
    for (int g = 0; g < 8; ++g)
        if (g < nv)
            out[(size_t)rws[g] * ODIM + lane] = acc[g];
}

__global__ void __launch_bounds__(256, 6)
fused(const int4*   __restrict__ x4,
      const int*    __restrict__ bucket,
      const float4* __restrict__ e0,
      const float4* __restrict__ e1,
      const float4* __restrict__ e2,
      const float*  __restrict__ emb3,
      const float*  __restrict__ W3,
      const float*  __restrict__ b3,
      const float*  __restrict__ emb4,
      const float*  __restrict__ W4,
      const float*  __restrict__ b4,
      float4*       __restrict__ out,
      int rows, int Tg4, int ngather)
{
    __shared__ __align__(16) float es[8][8 * PADK102];   // 26.6 KB
    __shared__ int sl3[256], sl4[256];
    __shared__ int sc3, sc4;

    int tid  = threadIdx.x;
    int warp = tid >> 5;
    int lane = tid & 31;

    if (blockIdx.x < NBUILD) {
        // ================= stage: project bucket-3/4 rows =================
        if (tid == 0) { sc3 = 0; sc4 = 0; }
        __syncthreads();

        int r  = blockIdx.x * 256 + tid;
        int bk = (r < rows) ? __ldg(&bucket[r]) : -1;

        unsigned m3 = __ballot_sync(0xffffffffu, bk == 3);
        unsigned m4 = __ballot_sync(0xffffffffu, bk == 4);
        unsigned lt = (1u << lane) - 1u;

        if (bk == 3) {
            int base = 0;
            int ldr = __ffs(m3) - 1;
            if (lane == ldr) base = atomicAdd(&sc3, __popc(m3));
            base = __shfl_sync(m3, base, ldr);
            sl3[base + __popc(m3 & lt)] = r;
        }
        if (bk == 4) {
            int base = 0;
            int ldr = __ffs(m4) - 1;
            if (lane == ldr) base = atomicAdd(&sc4, __popc(m4));
            base = __shfl_sync(m4, base, ldr);
            sl4[base + __popc(m4 & lt)] = r;
        }
        __syncthreads();

        int n3 = sc3, n4 = sc4;
        int n3g = (n3 + 7) >> 3;
        int n4g = (n4 + 7) >> 3;
        int ng  = n3g + n4g;

        float* proj = &g_proj[0];
        for (int g = warp; g < ng; g += 8) {
            if (g < n3g)
                proj_group<51,  PADK51 >(sl3, g * 8, n3, emb3, W3, b3,
                                         proj, es[warp], lane);
            else
                proj_group<102, PADK102>(sl4, (g - n3g) * 8, n4, emb4, W4, b4,
                                         proj, es[warp], lane);
        }

        __syncthreads();
        if (tid == 0) {
            __threadfence();
            atomicAdd(&g_done, 1);
        }
        return;
    }

    // ================= gather: 4 tokens per 8-thread group =================
    int gid = (blockIdx.x - NBUILD) * 256 + tid;
    int grp = gid >> 3;
    int c   = gid & 7;
    bool active = grp < Tg4;

    int idx[4], bk[4];
    if (active) {
        int4 ia = __ldg(&x4[grp]);
        idx[0] = ia.x; idx[1] = ia.y; idx[2] = ia.z; idx[3] = ia.w;

        #pragma unroll
        for (int j = 0; j < 4; ++j)
            bk[j] = __ldg(&bucket[idx[j]]);

        // bucket 0..2 rows: no dependency on projection — do them NOW.
        float4 v[4];
        bool   st[4];
        #pragma unroll
        for (int j = 0; j < 4; ++j) {
            st[j] = (bk[j] <= 2);
            const float4* t = (bk[j] == 0) ? e0 : (bk[j] == 1) ? e1 : e2;
            if (st[j]) v[j] = __ldg(&t[(size_t)idx[j] * 8 + c]);
        }
        #pragma unroll
        for (int j = 0; j < 4; ++j)
            if (st[j])
                __stcs(&out[(size_t)(grp * 4 + j) * 8 + c], v[j]);
    }

    // wait for projection producers
    if (*(volatile int*)&g_done < NBUILD) {
        while (*(volatile int*)&g_done < NBUILD)
            __nanosleep(128);
    }
    __threadfence();

    if (active) {
        const float4* pj = reinterpret_cast<const float4*>(&g_proj[0]);
        float4 v[4];
        bool   st[4];
        #pragma unroll
        for (int j = 0; j < 4; ++j) {
            st[j] = (bk[j] >= 3);
            if (st[j]) v[j] = __ldg(&pj[(size_t)idx[j] * 8 + c]);
        }
        #pragma unroll
        for (int j = 0; j < 4; ++j)
            if (st[j])
                __stcs(&out[(size_t)(grp * 4 + j) * 8 + c], v[j]);
    }

    // replay-safe reset: all threads of the block are past the spin here.
    __syncthreads();
    if (tid == 0) {
        int old = atomicAdd(&g_passed, 1);
        if (old == ngather - 1) {
            g_done = 0;
            __threadfence();
            g_passed = 0;
            __threadfence();
        }
    }
}

extern "C" void kernel_launch(void* const* d_in, const int* in_sizes, int n_in,
                              void* d_out, int out_size)
{
    const int*   x      = (const int*)  d_in[0];
    const int*   bucket = (const int*)  d_in[1];
    const float* emb0   = (const float*)d_in[2];
    const float* emb1   = (const float*)d_in[3];
    const float* emb2   = (const float*)d_in[4];
    const float* emb3   = (const float*)d_in[5];
    const float* emb4   = (const float*)d_in[6];
    const float* W3     = (const float*)d_in[7];
    const float* b3     = (const float*)d_in[8];
    const float* W4     = (const float*)d_in[9];
    const float* b4     = (const float*)d_in[10];

    const int T    = in_sizes[0];          // 1,048,576 tokens (multiple of 4)
    const int rows = in_sizes[1];          // 100,000

    const int Tg4     = T / 4;                       // 262,144 groups
    const int ngather = (Tg4 * 8 + 255) / 256;       // 8192 gather blocks

    fused<<<NBUILD + ngather, 256>>>(
        (const int4*)x, bucket,
        (const float4*)emb0, (const float4*)emb1, (const float4*)emb2,
        emb3, W3, b3, emb4, W4, b4,
        (float4*)d_out, rows, Tg4, ngather);
}

// round 15
// speedup vs baseline: 2.2562x; 1.7146x over previous
#include <cuda_runtime.h>

// ---------------------------------------------------------------------------
// FrequencyAwareEmbedding, round 15.  Revert to round-11 structure (best:
// 45.5us), stage_b re-tiled for 2x parallelism:
//   stage_b : block = 128-row tile, 128 threads (4 warps), 782 blocks.
//     scan   : ballot-compact rows into smem lists (sl3 / sl4 / slc).
//     proj   : warps round-robin dense groups of 8 rows (LDS.128 broadcast
//              quad loop); ~1 group per warp now (was ~2 with 256-row tiles).
//     copy   : warp-independent (no block sync): warp w copies rows
//              w*4+sub + i*16, 8 threads per row; warps with few proj groups
//              start copying early.
//   gather  : out[t] = g_all[x[t]], 8 tokens / 8-thread group (unchanged,
//             at its LSU/LTS floor).
// ---------------------------------------------------------------------------

#define NROWS 100000
#define ODIM  32

#define PADK51  52
#define PADK102 104

#define TILE    128
#define THREADS 128          // 4 warps
#define NWARP   4

__device__ __align__(256) float g_all[NROWS * ODIM];

// --- project one dense group of <=8 rows (row ids in smem list) ---
template <int K, int PADK>
__device__ __forceinline__ void proj_group(const int* __restrict__ slist,
                                           int gbase, int cnt,
                                           const float* __restrict__ emb,
                                           const float* __restrict__ W,
                                           const float* __restrict__ b,
                                           float* __restrict__ out,
                                           float* __restrict__ es,  // 8*PADK
                                           int lane)
{
    constexpr int CH = (PADK + 31) / 32;
    constexpr int Q  = (K + 3) / 4;

    int nv = cnt - gbase;
    if (nv > 8) nv = 8;

    int rws[8];
    #pragma unroll
    for (int g = 0; g < 8; ++g)
        rws[g] = slist[gbase + (g < nv ? g : 0)];

    // Stage rows into smem (coalesced), zero-fill pad [K, PADK).
    #pragma unroll
    for (int g = 0; g < 8; ++g) {
        #pragma unroll
        for (int ch = 0; ch < CH; ++ch) {
            int k = ch * 32 + lane;
            if (k < PADK)
                es[g * PADK + k] =
                    (k < K) ? __ldg(&emb[(size_t)rws[g] * K + k]) : 0.0f;
        }
    }
    __syncwarp();

    float bias = __ldg(&b[lane]);
    float acc[8];
    #pragma unroll
    for (int g = 0; g < 8; ++g) acc[g] = bias;

    #pragma unroll
    for (int q = 0; q < Q; ++q) {
        int k0 = q * 4;
        float w0 = __ldg(&W[(k0 + 0) * 32 + lane]);
        float w1 = (k0 + 1 < K) ? __ldg(&W[(k0 + 1) * 32 + lane]) : 0.0f;
        float w2 = (k0 + 2 < K) ? __ldg(&W[(k0 + 2) * 32 + lane]) : 0.0f;
        float w3 = (k0 + 3 < K) ? __ldg(&W[(k0 + 3) * 32 + lane]) : 0.0f;

        #pragma unroll
        for (int g = 0; g < 8; ++g) {
            float4 e4 = *reinterpret_cast<const float4*>(&es[g * PADK + k0]);
            acc[g] = fmaf(e4.x, w0, acc[g]);
            acc[g] = fmaf(e4.y, w1, acc[g]);
            acc[g] = fmaf(e4.z, w2, acc[g]);
            acc[g] = fmaf(e4.w, w3, acc[g]);
        }
    }
    __syncwarp();   // reads of es done before this warp restages

    #pragma unroll
    for (int g = 0; g < 8; ++g)
        if (g < nv)
            out[(size_t)rws[g] * ODIM + lane] = acc[g];
}

__global__ void __launch_bounds__(THREADS)
stage_b(const int*   __restrict__ bucket,
        const float* __restrict__ e0,
        const float* __restrict__ e1,
        const float* __restrict__ e2,
        const float* __restrict__ emb3,
        const float* __restrict__ W3,
        const float* __restrict__ b3,
        const float* __restrict__ emb4,
        const float* __restrict__ W4,
        const float* __restrict__ b4,
        float*       __restrict__ all_f,
        int rows)
{
    __shared__ __align__(16) float es[NWARP][8 * PADK102];   // 13.3 KB
    __shared__ int sl3[TILE], sl4[TILE], slc[TILE];
    __shared__ int sc3, sc4, scc;

    int tid  = threadIdx.x;
    int warp = tid >> 5;
    int lane = tid & 31;

    if (tid == 0) { sc3 = 0; sc4 = 0; scc = 0; }
    __syncthreads();

    // ---- scan + compact ----
    int r  = blockIdx.x * TILE + tid;
    int bk = (r < rows) ? __ldg(&bucket[r]) : -1;

    unsigned m3 = __ballot_sync(0xffffffffu, bk == 3);
    unsigned m4 = __ballot_sync(0xffffffffu, bk == 4);
    unsigned mc = __ballot_sync(0xffffffffu, bk >= 0 && bk <= 2);
    unsigned lt = (1u << lane) - 1u;

    if (bk == 3) {
        int base = 0;
        int ldr = __ffs(m3) - 1;
        if (lane == ldr) base = atomicAdd(&sc3, __popc(m3));
        base = __shfl_sync(m3, base, ldr);
        sl3[base + __popc(m3 & lt)] = r;
    }
    if (bk == 4) {
        int base = 0;
        int ldr = __ffs(m4) - 1;
        if (lane == ldr) base = atomicAdd(&sc4, __popc(m4));
        base = __shfl_sync(m4, base, ldr);
        sl4[base + __popc(m4 & lt)] = r;
    }
    if (bk >= 0 && bk <= 2) {
        int base = 0;
        int ldr = __ffs(mc) - 1;
        if (lane == ldr) base = atomicAdd(&scc, __popc(mc));
        base = __shfl_sync(mc, base, ldr);
        slc[base + __popc(mc & lt)] = (r << 2) | bk;
    }
    __syncthreads();

    int n3 = sc3, n4 = sc4, nc = scc;
    int n3g = (n3 + 7) >> 3;
    int n4g = (n4 + 7) >> 3;
    int ng  = n3g + n4g;

    // ---- projection first (latency-bound long pole) ----
    for (int g = warp; g < ng; g += NWARP) {
        if (g < n3g)
            proj_group<51,  PADK51 >(sl3, g * 8, n3, emb3, W3, b3,
                                     all_f, es[warp], lane);
        else
            proj_group<102, PADK102>(sl4, (g - n3g) * 8, n4, emb4, W4, b4,
                                     all_f, es[warp], lane);
    }

    // ---- copy (warp-independent; early-finishing warps start sooner) ----
    {
        int sub = lane >> 3;          // 0..3 : row slot within warp
        int c   = lane & 7;           // float4 column within row
        for (int j = warp * 4 + sub; j < nc; j += NWARP * 4) {
            int p  = slc[j];
            int rr = p >> 2, bb = p & 3;
            const float4* t = (bb == 0) ? (const float4*)e0
                            : (bb == 1) ? (const float4*)e1
                                        : (const float4*)e2;
            float4 v = __ldg(&t[(size_t)rr * 8 + c]);
            reinterpret_cast<float4*>(all_f)[(size_t)rr * 8 + c] = v;
        }
    }
}

// 8-thread group handles EIGHT tokens (MLP=8).
__global__ void gather_kernel(const int4*   __restrict__ x4,
                              const float4* __restrict__ tab,
                              float4*       __restrict__ out,
                              int Tg)
{
    int gid = blockIdx.x * blockDim.x + threadIdx.x;
    int grp = gid >> 3;
    if (grp >= Tg) return;
    int c = gid & 7;

    int4 ia = __ldg(&x4[(size_t)grp * 2 + 0]);
    int4 ib = __ldg(&x4[(size_t)grp * 2 + 1]);

    float4 v0 = __ldg(&tab[(size_t)ia.x * 8 + c]);
    float4 v1 = __ldg(&tab[(size_t)ia.y * 8 + c]);
    float4 v2 = __ldg(&tab[(size_t)ia.z * 8 + c]);
    float4 v3 = __ldg(&tab[(size_t)ia.w * 8 + c]);
    float4 v4 = __ldg(&tab[(size_t)ib.x * 8 + c]);
    float4 v5 = __ldg(&tab[(size_t)ib.y * 8 + c]);
    float4 v6 = __ldg(&tab[(size_t)ib.z * 8 + c]);
    float4 v7 = __ldg(&tab[(size_t)ib.w * 8 + c]);

    size_t base = (size_t)grp * 64 + c;
    __stcs(&out[base +  0], v0);
    __stcs(&out[base +  8], v1);
    __stcs(&out[base + 16], v2);
    __stcs(&out[base + 24], v3);
    __stcs(&out[base + 32], v4);
    __stcs(&out[base + 40], v5);
    __stcs(&out[base + 48], v6);
    __stcs(&out[base + 56], v7);
}

extern "C" void kernel_launch(void* const* d_in, const int* in_sizes, int n_in,
                              void* d_out, int out_size)
{
    const int*   x      = (const int*)  d_in[0];
    const int*   bucket = (const int*)  d_in[1];
    const float* emb0   = (const float*)d_in[2];
    const float* emb1   = (const float*)d_in[3];
    const float* emb2   = (const float*)d_in[4];
    const float* emb3   = (const float*)d_in[5];
    const float* emb4   = (const float*)d_in[6];
    const float* W3     = (const float*)d_in[7];
    const float* b3     = (const float*)d_in[8];
    const float* W4     = (const float*)d_in[9];
    const float* b4     = (const float*)d_in[10];

    const int T    = in_sizes[0];          // 1,048,576 tokens (multiple of 8)
    const int rows = in_sizes[1];          // 100,000

    float* all_f;
    cudaGetSymbolAddress((void**)&all_f, g_all);

    int sblocks = (rows + TILE - 1) / TILE;        // 782
    stage_b<<<sblocks, THREADS>>>(bucket, emb0, emb1, emb2,
                                  emb3, W3, b3, emb4, W4, b4, all_f, rows);

    const int Tg = T / 8;
    long long gthreads_total = (long long)Tg * 8;
    int gblocks = (int)((gthreads_total + 255) / 256);
    gather_kernel<<<gblocks, 256>>>((const int4*)x, (const float4*)all_f,
                                    (float4*)d_out, Tg);
}

// round 16
// speedup vs baseline: 2.4385x; 1.0808x over previous
#include <cuda_runtime.h>

// ---------------------------------------------------------------------------
// FrequencyAwareEmbedding, round 16.  TWO kernels + PDL overlap.
//   stage_b : proj-only (round-12 code, passed): smem-compact bucket-3/4 rows,
//             project into g_proj. Calls cudaTriggerProgrammaticLaunchCompletion
//             at block start so the gather launches concurrently.
//   gather  : launched with ProgrammaticStreamSerialization. 4 tokens per
//             8-thread group. Phase 1 (overlaps stage_b): idx -> bucket probe
//             -> bucket-0..2 rows straight from emb0/1/2. Then
//             cudaGridDependencySynchronize(). Phase 2: bucket-3/4 rows from
//             g_proj.
//   Separate kernels = separate register allocations (fixes round-13/14's
//   fat-kernel occupancy coupling); PDL = hardware wait (fixes the software
//   spin interference).
// ---------------------------------------------------------------------------

#define NROWS   100000
#define ODIM    32
#define PADK51  52
#define PADK102 104

__device__ __align__(256) float g_proj[NROWS * ODIM];  // rows of buckets 3,4

// --- project one dense group of <=8 rows (row ids in smem list) ---
template <int K, int PADK>
__device__ __forceinline__ void proj_group(const int* __restrict__ slist,
                                           int gbase, int cnt,
                                           const float* __restrict__ emb,
                                           const float* __restrict__ W,
                                           const float* __restrict__ b,
                                           float* __restrict__ out,
                                           float* __restrict__ es,  // 8*PADK
                                           int lane)
{
    constexpr int CH = (PADK + 31) / 32;
    constexpr int Q  = (K + 3) / 4;

    int nv = cnt - gbase;
    if (nv > 8) nv = 8;

    int rws[8];
    #pragma unroll
    for (int g = 0; g < 8; ++g)
        rws[g] = slist[gbase + (g < nv ? g : 0)];

    #pragma unroll
    for (int g = 0; g < 8; ++g) {
        #pragma unroll
        for (int ch = 0; ch < CH; ++ch) {
            int k = ch * 32 + lane;
            if (k < PADK)
                es[g * PADK + k] =
                    (k < K) ? __ldg(&emb[(size_t)rws[g] * K + k]) : 0.0f;
        }
    }
    __syncwarp();

    float bias = __ldg(&b[lane]);
    float acc[8];
    #pragma unroll
    for (int g = 0; g < 8; ++g) acc[g] = bias;

    #pragma unroll
    for (int q = 0; q < Q; ++q) {
        int k0 = q * 4;
        float w0 = __ldg(&W[(k0 + 0) * 32 + lane]);
        float w1 = (k0 + 1 < K) ? __ldg(&W[(k0 + 1) * 32 + lane]) : 0.0f;
        float w2 = (k0 + 2 < K) ? __ldg(&W[(k0 + 2) * 32 + lane]) : 0.0f;
        float w3 = (k0 + 3 < K) ? __ldg(&W[(k0 + 3) * 32 + lane]) : 0.0f;

        #pragma unroll
        for (int g = 0; g < 8; ++g) {
            float4 e4 = *reinterpret_cast<const float4*>(&es[g * PADK + k0]);
            acc[g] = fmaf(e4.x, w0, acc[g]);
            acc[g] = fmaf(e4.y, w1, acc[g]);
            acc[g] = fmaf(e4.z, w2, acc[g]);
            acc[g] = fmaf(e4.w, w3, acc[g]);
        }
    }
    __syncwarp();

    #pragma unroll
    for (int g = 0; g < 8; ++g)
        if (g < nv)
            out[(size_t)rws[g] * ODIM + lane] = acc[g];
}

__global__ void __launch_bounds__(256)
stage_b(const int*   __restrict__ bucket,
        const float* __restrict__ emb3,
        const float* __restrict__ W3,
        const float* __restrict__ b3,
        const float* __restrict__ emb4,
        const float* __restrict__ W4,
        const float* __restrict__ b4,
        float*       __restrict__ proj,
        int rows)
{
    // Let the dependent (gather) kernel launch immediately; it will
    // cudaGridDependencySynchronize() before reading g_proj.
    cudaTriggerProgrammaticLaunchCompletion();

    __shared__ __align__(16) float es[8][8 * PADK102];   // 26.6 KB
    __shared__ int sl3[256], sl4[256];
    __shared__ int sc3, sc4;

    int tid  = threadIdx.x;
    int warp = tid >> 5;
    int lane = tid & 31;

    if (tid == 0) { sc3 = 0; sc4 = 0; }
    __syncthreads();

    int r  = blockIdx.x * 256 + tid;
    int bk = (r < rows) ? __ldg(&bucket[r]) : -1;

    unsigned m3 = __ballot_sync(0xffffffffu, bk == 3);
    unsigned m4 = __ballot_sync(0xffffffffu, bk == 4);
    unsigned lt = (1u << lane) - 1u;

    if (bk == 3) {
        int base = 0;
        int ldr = __ffs(m3) - 1;
        if (lane == ldr) base = atomicAdd(&sc3, __popc(m3));
        base = __shfl_sync(m3, base, ldr);
        sl3[base + __popc(m3 & lt)] = r;
    }
    if (bk == 4) {
        int base = 0;
        int ldr = __ffs(m4) - 1;
        if (lane == ldr) base = atomicAdd(&sc4, __popc(m4));
        base = __shfl_sync(m4, base, ldr);
        sl4[base + __popc(m4 & lt)] = r;
    }
    __syncthreads();

    int n3 = sc3, n4 = sc4;
    int n3g = (n3 + 7) >> 3;
    int n4g = (n4 + 7) >> 3;
    int ng  = n3g + n4g;

    for (int g = warp; g < ng; g += 8) {
        if (g < n3g)
            proj_group<51,  PADK51 >(sl3, g * 8, n3, emb3, W3, b3,
                                     proj, es[warp], lane);
        else
            proj_group<102, PADK102>(sl4, (g - n3g) * 8, n4, emb4, W4, b4,
                                     proj, es[warp], lane);
    }
}

// 8-thread group handles FOUR tokens. Phase 1 overlaps stage_b.
__global__ void __launch_bounds__(256)
gather_kernel(const int4*   __restrict__ x4,
              const int*    __restrict__ bucket,
              const float4* __restrict__ e0,
              const float4* __restrict__ e1,
              const float4* __restrict__ e2,
              float4*       __restrict__ out,
              int Tg4)
{
    int gid = blockIdx.x * blockDim.x + threadIdx.x;
    int grp = gid >> 3;
    int c   = gid & 7;
    bool active = grp < Tg4;

    int idx[4], bk[4];
    if (active) {
        int4 ia = __ldg(&x4[grp]);
        idx[0] = ia.x; idx[1] = ia.y; idx[2] = ia.z; idx[3] = ia.w;

        #pragma unroll
        for (int j = 0; j < 4; ++j)
            bk[j] = __ldg(&bucket[idx[j]]);

        // Phase 1: bucket-0..2 rows (independent of projection).
        float4 v[4];
        bool   st[4];
        #pragma unroll
        for (int j = 0; j < 4; ++j) {
            st[j] = (bk[j] <= 2);
            const float4* t = (bk[j] == 0) ? e0 : (bk[j] == 1) ? e1 : e2;
            if (st[j]) v[j] = __ldg(&t[(size_t)idx[j] * 8 + c]);
        }
        #pragma unroll
        for (int j = 0; j < 4; ++j)
            if (st[j])
                __stcs(&out[(size_t)(grp * 4 + j) * 8 + c], v[j]);
    }

    // Wait until stage_b's g_proj writes are visible (PDL dependency).
    cudaGridDependencySynchronize();

    if (active) {
        const float4* pj = reinterpret_cast<const float4*>(&g_proj[0]);
        float4 v[4];
        bool   st[4];
        #pragma unroll
        for (int j = 0; j < 4; ++j) {
            st[j] = (bk[j] >= 3);
            if (st[j]) v[j] = __ldg(&pj[(size_t)idx[j] * 8 + c]);
        }
        #pragma unroll
        for (int j = 0; j < 4; ++j)
            if (st[j])
                __stcs(&out[(size_t)(grp * 4 + j) * 8 + c], v[j]);
    }
}

extern "C" void kernel_launch(void* const* d_in, const int* in_sizes, int n_in,
                              void* d_out, int out_size)
{
    const int*   x      = (const int*)  d_in[0];
    const int*   bucket = (const int*)  d_in[1];
    const float* emb0   = (const float*)d_in[2];
    const float* emb1   = (const float*)d_in[3];
    const float* emb2   = (const float*)d_in[4];
    const float* emb3   = (const float*)d_in[5];
    const float* emb4   = (const float*)d_in[6];
    const float* W3     = (const float*)d_in[7];
    const float* b3     = (const float*)d_in[8];
    const float* W4     = (const float*)d_in[9];
    const float* b4     = (const float*)d_in[10];

    const int T    = in_sizes[0];          // 1,048,576 tokens (multiple of 4)
    const int rows = in_sizes[1];          // 100,000

    float* proj;
    cudaGetSymbolAddress((void**)&proj, g_proj);

    int sblocks = (rows + 255) / 256;      // 391
    stage_b<<<sblocks, 256>>>(bucket, emb3, W3, b3, emb4, W4, b4, proj, rows);

    const int Tg4 = T / 4;                          // 262,144 groups
    int gblocks = (int)(((long long)Tg4 * 8 + 255) / 256);   // 8192

    cudaLaunchConfig_t cfg = {};
    cfg.gridDim  = dim3((unsigned)gblocks, 1, 1);
    cfg.blockDim = dim3(256, 1, 1);
    cfg.dynamicSmemBytes = 0;
    cfg.stream = 0;   // legacy default stream (same one the harness captures)

    cudaLaunchAttribute attrs[1];
    attrs[0].id = cudaLaunchAttributeProgrammaticStreamSerialization;
    attrs[0].val.programmaticStreamSerializationAllowed = 1;
    cfg.attrs    = attrs;
    cfg.numAttrs = 1;

    cudaLaunchKernelEx(&cfg, gather_kernel,
                       (const int4*)x, bucket,
                       (const float4*)emb0, (const float4*)emb1,
                       (const float4*)emb2,
                       (float4*)d_out, Tg4);
}